// round 3
// baseline (speedup 1.0000x reference)
#include <cuda_runtime.h>
#include <cuda_bf16.h>
#include <math.h>

// Problem constants (hardcoded to this problem's shapes)
#define B_ 2
#define S_ 4096
#define H_ 16
#define DK 128
#define DV 128
#define CHK 64
#define NCH (S_ / CHK)          // 64 chunks
#define NBH (B_ * H_)           // 32
#define NTILE (NBH * NCH)       // 2048 tiles

// Scratch (device globals: allocation-free rule)
__device__ float g_u   [NTILE * CHK * DV];   // 64 MB
__device__ float g_kcd [NTILE * CHK * DK];   // 64 MB
__device__ float g_qg  [NTILE * CHK * DK];   // 64 MB
__device__ float g_kd  [NTILE * CHK * DK];   // 64 MB
__device__ float g_attn[NTILE * CHK * CHK];  // 32 MB
__device__ float g_egl [NTILE];              // exp(g_last) per tile

#define P1_SMEM_FLOATS (8192 + 8256 + 8192 + 4096 + 4096 + 64*5 + 128)
#define P2_SMEM_FLOATS (4096 + 8192 + 8192 + 8192 + 4096 + 2048 + 2048)

// ---------------------------------------------------------------------------
// Phase 1: per-(b,h,chunk) preprocessing. grid = 2048, block = 256.
// ---------------------------------------------------------------------------
__global__ __launch_bounds__(256, 1)
void p1_kernel(const float* __restrict__ q_in, const float* __restrict__ k_in,
               const float* __restrict__ v_in, const float* __restrict__ g_in,
               const float* __restrict__ b_in)
{
    extern __shared__ float sm[];
    float* sq   = sm;              // [64][128]
    float* sk   = sq + 8192;       // [64][129]  (pitch 129: conflict-free col access)
    float* sv   = sk + 8256;       // [64][128]  (prescaled by beta)
    float* sA   = sv + 8192;       // [64][64]
    float* sX   = sA + 4096;       // [64][64]   Tinv
    float* s_g    = sX + 4096;     // 64
    float* s_beta = s_g + 64;      // 64
    float* s_gcs  = s_beta + 64;   // 64
    float* s_ec   = s_gcs + 64;    // 64 exp(gcs)
    float* s_el   = s_ec + 64;     // 64 exp(g_last - gcs)
    float* s_rn   = s_el + 64;     // 128: [0..63] q-norm*Dk^-.5, [64..127] k-norm

    const int t   = blockIdx.x;
    const int n   = t & (NCH - 1);
    const int bh  = t >> 6;
    const int b   = bh >> 4;
    const int h   = bh & 15;
    const int tid = threadIdx.x;

    const size_t base = ((size_t)(b * S_ + n * CHK) * H_ + h) * DK;

    // Load q/k/v tile (rows stride H_*DK = 2048 floats in global)
    for (int p = tid; p < 2048; p += 256) {
        int row = p >> 5;
        int c   = (p & 31) * 4;
        float4 qv = *(const float4*)&q_in[base + (size_t)row * 2048 + c];
        float4 kv = *(const float4*)&k_in[base + (size_t)row * 2048 + c];
        float4 vv = *(const float4*)&v_in[base + (size_t)row * 2048 + c];
        sq[row * 128 + c + 0] = qv.x; sq[row * 128 + c + 1] = qv.y;
        sq[row * 128 + c + 2] = qv.z; sq[row * 128 + c + 3] = qv.w;
        sk[row * 129 + c + 0] = kv.x; sk[row * 129 + c + 1] = kv.y;
        sk[row * 129 + c + 2] = kv.z; sk[row * 129 + c + 3] = kv.w;
        sv[row * 128 + c + 0] = vv.x; sv[row * 128 + c + 1] = vv.y;
        sv[row * 128 + c + 2] = vv.z; sv[row * 128 + c + 3] = vv.w;
    }
    if (tid < 64) {
        int s = n * CHK + tid;
        s_g[tid]    = g_in[(size_t)(b * S_ + s) * H_ + h];
        s_beta[tid] = b_in[(size_t)(b * S_ + s) * H_ + h];
    }
    __syncthreads();

    // cumsum of g (cheap serial)
    if (tid == 0) {
        float c = 0.f;
        for (int i = 0; i < 64; i++) { c += s_g[i]; s_gcs[i] = c; }
    }
    // row L2 norms: 4 threads per row
    {
        int row = tid >> 2, part = tid & 3;
        float aq = 0.f, ak = 0.f;
        for (int d = part * 32; d < part * 32 + 32; d++) {
            float a = sq[row * 128 + d]; aq += a * a;
            float c = sk[row * 129 + d]; ak += c * c;
        }
        aq += __shfl_xor_sync(0xffffffff, aq, 1);
        aq += __shfl_xor_sync(0xffffffff, aq, 2);
        ak += __shfl_xor_sync(0xffffffff, ak, 1);
        ak += __shfl_xor_sync(0xffffffff, ak, 2);
        if (part == 0) {
            s_rn[row]      = rsqrtf(aq + 1e-6f) * 0.08838834764831843f; // * Dk^-0.5
            s_rn[64 + row] = rsqrtf(ak + 1e-6f);
        }
    }
    __syncthreads();

    // scale q, k; prescale v by beta; exp tables
    for (int p = tid; p < 8192; p += 256) {
        int row = p >> 7, c = p & 127;
        sq[p] *= s_rn[row];
        sk[row * 129 + c] *= s_rn[64 + row];
        sv[p] *= s_beta[row];
    }
    if (tid < 64) {
        s_ec[tid] = expf(s_gcs[tid]);
        s_el[tid] = expf(s_gcs[63] - s_gcs[tid]);
    }
    __syncthreads();

    // A = strict_tril(kb . k^T * decay);  attn = tril(q . k^T * decay) -> global
    const int w = tid >> 5, l = tid & 31;
    {
        float accA[8][2], accQ[8][2];
        #pragma unroll
        for (int r = 0; r < 8; r++) {
            accA[r][0] = accA[r][1] = 0.f;
            accQ[r][0] = accQ[r][1] = 0.f;
        }
        for (int d = 0; d < 128; d++) {
            float k0 = sk[l * 129 + d];
            float k1 = sk[(l + 32) * 129 + d];
            #pragma unroll
            for (int r = 0; r < 8; r++) {
                float ki = sk[(w * 8 + r) * 129 + d];
                float qi = sq[(w * 8 + r) * 128 + d];
                accA[r][0] += ki * k0; accA[r][1] += ki * k1;
                accQ[r][0] += qi * k0; accQ[r][1] += qi * k1;
            }
        }
        float* gattn = g_attn + (size_t)t * (CHK * CHK);
        #pragma unroll
        for (int r = 0; r < 8; r++) {
            int i = w * 8 + r;
            #pragma unroll
            for (int c2 = 0; c2 < 2; c2++) {
                int jj  = l + c2 * 32;
                float dec = (i >= jj) ? expf(s_gcs[i] - s_gcs[jj]) : 0.f;
                sA[i * 64 + jj]     = (i > jj) ? accA[r][c2] * s_beta[i] * dec : 0.f;
                gattn[i * 64 + jj]  = accQ[r][c2] * dec;  // dec=0 masks upper; diag dec=1
            }
        }
    }
    __syncthreads();

    // Tinv = (I + A)^-1 (unit lower), forward substitution; thread j = column
    if (tid < 64) sX[tid] = (tid == 0) ? 1.f : 0.f;
    __syncthreads();
    for (int i = 1; i < 64; i++) {
        if (tid < 64) {
            int j = tid;
            float x;
            if (j > i)       x = 0.f;
            else if (j == i) x = 1.f;
            else {
                float a0 = 0.f, a1 = 0.f, a2 = 0.f, a3 = 0.f;
                int m = j;
                for (; m + 3 < i; m += 4) {
                    a0 -= sA[i * 64 + m + 0] * sX[(m + 0) * 64 + j];
                    a1 -= sA[i * 64 + m + 1] * sX[(m + 1) * 64 + j];
                    a2 -= sA[i * 64 + m + 2] * sX[(m + 2) * 64 + j];
                    a3 -= sA[i * 64 + m + 3] * sX[(m + 3) * 64 + j];
                }
                for (; m < i; m++) a0 -= sA[i * 64 + m] * sX[m * 64 + j];
                x = (a0 + a1) + (a2 + a3);
            }
            sX[i * 64 + j] = x;
        }
        __syncthreads();
    }

    // u = Tinv @ (v*beta);  kcd = Tinv @ (k * beta * e^gcs)
    {
        float accU[8][4], accK[8][4];
        #pragma unroll
        for (int r = 0; r < 8; r++)
            #pragma unroll
            for (int dd = 0; dd < 4; dd++) { accU[r][dd] = 0.f; accK[r][dd] = 0.f; }

        for (int c = 0; c < 64; c++) {
            float ck = s_beta[c] * s_ec[c];
            float v0 = sv[c * 128 + l],      v1 = sv[c * 128 + l + 32];
            float v2 = sv[c * 128 + l + 64], v3 = sv[c * 128 + l + 96];
            float k0 = sk[c * 129 + l],      k1 = sk[c * 129 + l + 32];
            float k2 = sk[c * 129 + l + 64], k3 = sk[c * 129 + l + 96];
            #pragma unroll
            for (int r = 0; r < 8; r++) {
                float x  = sX[(w * 8 + r) * 64 + c];
                float xk = x * ck;
                accU[r][0] += x * v0;  accU[r][1] += x * v1;
                accU[r][2] += x * v2;  accU[r][3] += x * v3;
                accK[r][0] += xk * k0; accK[r][1] += xk * k1;
                accK[r][2] += xk * k2; accK[r][3] += xk * k3;
            }
        }
        float* gu = g_u   + (size_t)t * (CHK * DV);
        float* gk = g_kcd + (size_t)t * (CHK * DK);
        #pragma unroll
        for (int r = 0; r < 8; r++) {
            int i = w * 8 + r;
            #pragma unroll
            for (int dd = 0; dd < 4; dd++) {
                gu[i * 128 + l + dd * 32] = accU[r][dd];
                gk[i * 128 + l + dd * 32] = accK[r][dd];
            }
        }
    }

    // qg = q * e^gcs; kd = k * e^(g_last - gcs); exp(g_last)
    {
        float* gq = g_qg + (size_t)t * (CHK * DK);
        float* gd = g_kd + (size_t)t * (CHK * DK);
        for (int p = tid; p < 8192; p += 256) {
            int row = p >> 7, c = p & 127;
            gq[p] = sq[p] * s_ec[row];
            gd[p] = sk[row * 129 + c] * s_el[row];
        }
        if (tid == 0) g_egl[t] = expf(s_gcs[63]);
    }
}

// ---------------------------------------------------------------------------
// Phase 2: sequential scan. grid = 128 (32 bh x 4 Dv-blocks), block = 256.
// ---------------------------------------------------------------------------
__global__ __launch_bounds__(256, 1)
void p2_kernel(float* __restrict__ out)
{
    extern __shared__ float sm[];
    float* s_state = sm;                 // [128][32]
    float* s_kcd   = s_state + 4096;     // [64][128]
    float* s_qg    = s_kcd + 8192;       // [64][128]
    float* s_kd    = s_qg + 8192;        // [64][128]
    float* s_attn  = s_kd + 8192;        // [64][64]
    float* s_u     = s_attn + 4096;      // [64][32]
    float* s_vn    = s_u + 2048;         // [64][32]

    const int bx = blockIdx.x;
    const int bh = bx >> 2;
    const int vb = bx & 3;
    const int b  = bh >> 4;
    const int h  = bh & 15;
    const int tid = threadIdx.x;
    const int w = tid >> 5, l = tid & 31;

    for (int p = tid; p < 4096; p += 256) s_state[p] = 0.f;
    __syncthreads();

    for (int n = 0; n < NCH; n++) {
        const size_t t = (size_t)bh * NCH + n;

        // stage this chunk's matrices
        {
            const float4* gk = (const float4*)(g_kcd + t * (CHK * DK));
            const float4* gq = (const float4*)(g_qg  + t * (CHK * DK));
            const float4* gd = (const float4*)(g_kd  + t * (CHK * DK));
            const float4* ga = (const float4*)(g_attn + t * (CHK * CHK));
            for (int p = tid; p < 2048; p += 256) {
                ((float4*)s_kcd)[p] = gk[p];
                ((float4*)s_qg)[p]  = gq[p];
                ((float4*)s_kd)[p]  = gd[p];
            }
            for (int p = tid; p < 1024; p += 256) ((float4*)s_attn)[p] = ga[p];
            for (int p = tid; p < 512; p += 256) {
                int row = p >> 3, c4 = (p & 7) * 4;
                ((float4*)s_u)[p] =
                    *(const float4*)&g_u[t * (CHK * DV) + row * 128 + vb * 32 + c4];
            }
        }
        __syncthreads();

        // v_new = u - kcd @ state ; o1 = qg @ state
        float accV[8], accO[8];
        #pragma unroll
        for (int r = 0; r < 8; r++) {
            accV[r] = s_u[(w * 8 + r) * 32 + l];
            accO[r] = 0.f;
        }
        for (int k = 0; k < 128; k += 4) {
            float st0 = s_state[(k + 0) * 32 + l];
            float st1 = s_state[(k + 1) * 32 + l];
            float st2 = s_state[(k + 2) * 32 + l];
            float st3 = s_state[(k + 3) * 32 + l];
            #pragma unroll
            for (int r = 0; r < 8; r++) {
                float4 kc = *(const float4*)&s_kcd[(w * 8 + r) * 128 + k];
                float4 qc = *(const float4*)&s_qg[(w * 8 + r) * 128 + k];
                accV[r] -= kc.x * st0; accV[r] -= kc.y * st1;
                accV[r] -= kc.z * st2; accV[r] -= kc.w * st3;
                accO[r] += qc.x * st0; accO[r] += qc.y * st1;
                accO[r] += qc.z * st2; accO[r] += qc.w * st3;
            }
        }
        #pragma unroll
        for (int r = 0; r < 8; r++) s_vn[(w * 8 + r) * 32 + l] = accV[r];
        __syncthreads();

        // o += attn @ v_new ; write out
        for (int c = 0; c < 64; c += 4) {
            float v0 = s_vn[(c + 0) * 32 + l];
            float v1 = s_vn[(c + 1) * 32 + l];
            float v2 = s_vn[(c + 2) * 32 + l];
            float v3 = s_vn[(c + 3) * 32 + l];
            #pragma unroll
            for (int r = 0; r < 8; r++) {
                float4 a = *(const float4*)&s_attn[(w * 8 + r) * 64 + c];
                accO[r] += a.x * v0; accO[r] += a.y * v1;
                accO[r] += a.z * v2; accO[r] += a.w * v3;
            }
        }
        {
            const size_t obase =
                ((size_t)(b * S_ + n * CHK) * H_ + h) * DV + vb * 32;
            #pragma unroll
            for (int r = 0; r < 8; r++)
                out[obase + (size_t)(w * 8 + r) * (H_ * DV) + l] = accO[r];
        }

        // state = state * e^{g_last} + kd^T @ v_new   (each thread owns 16 rows, col l)
        {
            float eg = g_egl[t];
            float sacc[16];
            #pragma unroll
            for (int rr = 0; rr < 16; rr++)
                sacc[rr] = s_state[(w * 16 + rr) * 32 + l] * eg;
            for (int c = 0; c < 64; c++) {
                float vn = s_vn[c * 32 + l];
                #pragma unroll
                for (int r4 = 0; r4 < 4; r4++) {
                    float4 kd = *(const float4*)&s_kd[c * 128 + w * 16 + r4 * 4];
                    sacc[r4 * 4 + 0] += kd.x * vn;
                    sacc[r4 * 4 + 1] += kd.y * vn;
                    sacc[r4 * 4 + 2] += kd.z * vn;
                    sacc[r4 * 4 + 3] += kd.w * vn;
                }
            }
            #pragma unroll
            for (int rr = 0; rr < 16; rr++)
                s_state[(w * 16 + rr) * 32 + l] = sacc[rr];
        }
        __syncthreads();
    }
}

// ---------------------------------------------------------------------------
extern "C" void kernel_launch(void* const* d_in, const int* in_sizes, int n_in,
                              void* d_out, int out_size)
{
    const float* q    = (const float*)d_in[0];
    const float* k    = (const float*)d_in[1];
    const float* v    = (const float*)d_in[2];
    const float* g    = (const float*)d_in[3];
    const float* beta = (const float*)d_in[4];
    float* out = (float*)d_out;

    const int p1s = P1_SMEM_FLOATS * 4;
    const int p2s = P2_SMEM_FLOATS * 4;
    cudaFuncSetAttribute(p1_kernel, cudaFuncAttributeMaxDynamicSharedMemorySize, p1s);
    cudaFuncSetAttribute(p2_kernel, cudaFuncAttributeMaxDynamicSharedMemorySize, p2s);

    p1_kernel<<<NTILE, 256, p1s>>>(q, k, v, g, beta);
    p2_kernel<<<NBH * 4, 256, p2s>>>(out);
}

// round 5
// speedup vs baseline: 2.2613x; 2.2613x over previous
#include <cuda_runtime.h>
#include <cuda_bf16.h>
#include <math.h>

// Problem constants
#define B_ 2
#define S_ 4096
#define H_ 16
#define DK 128
#define DV 128
#define CHK 64
#define NCH (S_ / CHK)          // 64 chunks
#define NBH (B_ * H_)           // 32
#define NTILE (NBH * NCH)       // 2048 tiles

// Scratch (device globals: allocation-free rule)
__device__ float g_u   [NTILE * CHK * DV];   // 64 MB
__device__ float g_kcd [NTILE * CHK * DK];   // 64 MB
__device__ float g_qg  [NTILE * CHK * DK];   // 64 MB
__device__ float g_kd  [NTILE * CHK * DK];   // 64 MB
__device__ float g_attn[NTILE * CHK * CHK];  // 32 MB
__device__ float g_egl [NTILE];              // exp(g_last) per tile

// p1 smem: sq 8192 + sk 8256 + sv 8192 + sA 4096 + sU 16384 + 512 misc
#define P1_SMEM_FLOATS (8192 + 8256 + 8192 + 4096 + 16384 + 512)
// p2 smem: state 4096 + kcd 8192 + qg 8192 + kd 8192 + attn 4096 + u 2048 + vn 2048
#define P2_SMEM_FLOATS (4096 + 8192 + 8192 + 8192 + 4096 + 2048 + 2048)

// ---------------------------------------------------------------------------
// Phase 1: per-(b,h,chunk) preprocessing. grid = 2048, block = 256.
// ---------------------------------------------------------------------------
__global__ __launch_bounds__(256, 1)
void p1_kernel(const float* __restrict__ q_in, const float* __restrict__ k_in,
               const float* __restrict__ v_in, const float* __restrict__ g_in,
               const float* __restrict__ b_in)
{
    extern __shared__ float sm[];
    float* sq   = sm;              // [64][128]
    float* sk   = sq + 8192;       // [64][129]
    float* sv   = sk + 8256;       // [64][128]  (prescaled by beta)
    float* sA   = sv + 8192;       // [64][64]
    float* sU   = sA + 4096;       // [64][256]  solve panel: cols 0-127 u, 128-255 kcd
    float* s_g    = sU + 16384;    // 64
    float* s_beta = s_g + 64;      // 64
    float* s_gcs  = s_beta + 64;   // 64
    float* s_ec   = s_gcs + 64;    // 64 exp(gcs)
    float* s_el   = s_ec + 64;     // 64 exp(g_last - gcs)
    float* s_bfe  = s_el + 64;     // 64 beta*exp(gcs)
    float* s_rn   = s_bfe + 64;    // 128

    const int t   = blockIdx.x;
    const int n   = t & (NCH - 1);
    const int bh  = t >> 6;
    const int b   = bh >> 4;
    const int h   = bh & 15;
    const int tid = threadIdx.x;

    const size_t base = ((size_t)(b * S_ + n * CHK) * H_ + h) * DK;

    // Load q/k/v tile
    for (int p = tid; p < 2048; p += 256) {
        int row = p >> 5;
        int c   = (p & 31) * 4;
        float4 qv = *(const float4*)&q_in[base + (size_t)row * 2048 + c];
        float4 kv = *(const float4*)&k_in[base + (size_t)row * 2048 + c];
        float4 vv = *(const float4*)&v_in[base + (size_t)row * 2048 + c];
        sq[row * 128 + c + 0] = qv.x; sq[row * 128 + c + 1] = qv.y;
        sq[row * 128 + c + 2] = qv.z; sq[row * 128 + c + 3] = qv.w;
        sk[row * 129 + c + 0] = kv.x; sk[row * 129 + c + 1] = kv.y;
        sk[row * 129 + c + 2] = kv.z; sk[row * 129 + c + 3] = kv.w;
        sv[row * 128 + c + 0] = vv.x; sv[row * 128 + c + 1] = vv.y;
        sv[row * 128 + c + 2] = vv.z; sv[row * 128 + c + 3] = vv.w;
    }
    if (tid < 64) {
        int s = n * CHK + tid;
        s_g[tid]    = g_in[(size_t)(b * S_ + s) * H_ + h];
        s_beta[tid] = b_in[(size_t)(b * S_ + s) * H_ + h];
    }
    __syncthreads();

    // cumsum of g (cheap serial; runs alongside the norm phase)
    if (tid == 0) {
        float c = 0.f;
        for (int i = 0; i < 64; i++) { c += s_g[i]; s_gcs[i] = c; }
    }
    // row L2 norms: 4 threads per row
    {
        int row = tid >> 2, part = tid & 3;
        float aq = 0.f, ak = 0.f;
        for (int d = part * 32; d < part * 32 + 32; d++) {
            float a = sq[row * 128 + d]; aq += a * a;
            float c = sk[row * 129 + d]; ak += c * c;
        }
        aq += __shfl_xor_sync(0xffffffff, aq, 1);
        aq += __shfl_xor_sync(0xffffffff, aq, 2);
        ak += __shfl_xor_sync(0xffffffff, ak, 1);
        ak += __shfl_xor_sync(0xffffffff, ak, 2);
        if (part == 0) {
            s_rn[row]      = rsqrtf(aq + 1e-6f) * 0.08838834764831843f; // * Dk^-0.5
            s_rn[64 + row] = rsqrtf(ak + 1e-6f);
        }
    }
    __syncthreads();

    // scale q, k; prescale v by beta; exp tables
    for (int p = tid; p < 8192; p += 256) {
        int row = p >> 7, c = p & 127;
        sq[p] *= s_rn[row];
        sk[row * 129 + c] *= s_rn[64 + row];
        sv[p] *= s_beta[row];
    }
    if (tid < 64) {
        float e = expf(s_gcs[tid]);
        s_ec[tid]  = e;
        s_el[tid]  = expf(s_gcs[63] - s_gcs[tid]);
        s_bfe[tid] = s_beta[tid] * e;
    }
    __syncthreads();

    // A = strict_tril(kb . k^T * decay);  attn = tril(q . k^T * decay) -> global
    const int w = tid >> 5, l = tid & 31;
    {
        float accA[8][2], accQ[8][2];
        #pragma unroll
        for (int r = 0; r < 8; r++) {
            accA[r][0] = accA[r][1] = 0.f;
            accQ[r][0] = accQ[r][1] = 0.f;
        }
        for (int d = 0; d < 128; d++) {
            float k0 = sk[l * 129 + d];
            float k1 = sk[(l + 32) * 129 + d];
            #pragma unroll
            for (int r = 0; r < 8; r++) {
                float ki = sk[(w * 8 + r) * 129 + d];
                float qi = sq[(w * 8 + r) * 128 + d];
                accA[r][0] += ki * k0; accA[r][1] += ki * k1;
                accQ[r][0] += qi * k0; accQ[r][1] += qi * k1;
            }
        }
        float* gattn = g_attn + (size_t)t * (CHK * CHK);
        #pragma unroll
        for (int r = 0; r < 8; r++) {
            int i = w * 8 + r;
            #pragma unroll
            for (int c2 = 0; c2 < 2; c2++) {
                int jj  = l + c2 * 32;
                float dec = (i >= jj) ? expf(s_gcs[i] - s_gcs[jj]) : 0.f;
                sA[i * 64 + jj]     = (i > jj) ? accA[r][c2] * s_beta[i] * dec : 0.f;
                gattn[i * 64 + jj]  = accQ[r][c2] * dec;
            }
        }
    }
    __syncthreads();

    // Fused forward substitution: (I + A) X = [ v*beta | k*beta*e^gcs ]
    // One column per thread, zero barriers. Columns 0-127 -> u, 128-255 -> kcd.
    {
        const int c  = tid;
        const int cc = c & 127;
        const bool isV = (c < 128);
        for (int i = 0; i < 64; i++) {
            float acc = isV ? sv[i * 128 + cc]
                            : sk[i * 129 + cc] * s_bfe[i];
            float a0 = 0.f, a1 = 0.f, a2 = 0.f, a3 = 0.f;
            int m = 0;
            for (; m + 3 < i; m += 4) {
                a0 += sA[i * 64 + m + 0] * sU[(m + 0) * 256 + c];
                a1 += sA[i * 64 + m + 1] * sU[(m + 1) * 256 + c];
                a2 += sA[i * 64 + m + 2] * sU[(m + 2) * 256 + c];
                a3 += sA[i * 64 + m + 3] * sU[(m + 3) * 256 + c];
            }
            for (; m < i; m++) a0 += sA[i * 64 + m] * sU[m * 256 + c];
            float val = acc - ((a0 + a1) + (a2 + a3));
            sU[i * 256 + c] = val;
            // stream result straight to global (coalesced per 128-thread half)
            if (isV) g_u  [(size_t)t * (CHK * DV) + i * 128 + cc] = val;
            else     g_kcd[(size_t)t * (CHK * DK) + i * 128 + cc] = val;
        }
    }

    // qg = q * e^gcs; kd = k * e^(g_last - gcs); exp(g_last)
    {
        float* gq = g_qg + (size_t)t * (CHK * DK);
        float* gd = g_kd + (size_t)t * (CHK * DK);
        for (int p = tid; p < 8192; p += 256) {
            int row = p >> 7, c = p & 127;
            gq[p] = sq[p] * s_ec[row];
            gd[p] = sk[row * 129 + c] * s_el[row];
        }
        if (tid == 0) g_egl[t] = expf(s_gcs[63]);
    }
}

// ---------------------------------------------------------------------------
// Phase 2: sequential scan. grid = 128 (32 bh x 4 Dv-blocks), block = 512.
// ---------------------------------------------------------------------------
__global__ __launch_bounds__(512, 1)
void p2_kernel(float* __restrict__ out)
{
    extern __shared__ float sm[];
    float* s_state = sm;                 // [128][32]
    float* s_kcd   = s_state + 4096;     // [64][128]
    float* s_qg    = s_kcd + 8192;       // [64][128]
    float* s_kd    = s_qg + 8192;        // [64][128]
    float* s_attn  = s_kd + 8192;        // [64][64]
    float* s_u     = s_attn + 4096;      // [64][32]
    float* s_vn    = s_u + 2048;         // [64][32]

    const int bx = blockIdx.x;
    const int bh = bx >> 2;
    const int vb = bx & 3;
    const int b  = bh >> 4;
    const int h  = bh & 15;
    const int tid = threadIdx.x;
    const int w = tid >> 5, l = tid & 31;   // 16 warps

    for (int p = tid; p < 4096; p += 512) s_state[p] = 0.f;
    __syncthreads();

    for (int n = 0; n < NCH; n++) {
        const size_t t = (size_t)bh * NCH + n;

        // stage this chunk's matrices (512 threads)
        {
            const float4* gk = (const float4*)(g_kcd + t * (CHK * DK));
            const float4* gq = (const float4*)(g_qg  + t * (CHK * DK));
            const float4* gd = (const float4*)(g_kd  + t * (CHK * DK));
            const float4* ga = (const float4*)(g_attn + t * (CHK * CHK));
            #pragma unroll
            for (int it = 0; it < 4; it++) {
                int p = tid + it * 512;
                ((float4*)s_kcd)[p] = gk[p];
                ((float4*)s_qg)[p]  = gq[p];
                ((float4*)s_kd)[p]  = gd[p];
            }
            #pragma unroll
            for (int it = 0; it < 2; it++) {
                int p = tid + it * 512;
                ((float4*)s_attn)[p] = ga[p];
            }
            {
                int p = tid;
                if (p < 512) {
                    int row = p >> 3, c4 = (p & 7) * 4;
                    ((float4*)s_u)[p] =
                        *(const float4*)&g_u[t * (CHK * DV) + row * 128 + vb * 32 + c4];
                }
            }
        }
        __syncthreads();

        // Phase A: v_new = u - kcd @ state ; o1 = qg @ state  (4 rows per warp)
        const int r0 = w * 4;
        float accV[4], accO[4];
        #pragma unroll
        for (int r = 0; r < 4; r++) {
            accV[r] = s_u[(r0 + r) * 32 + l];
            accO[r] = 0.f;
        }
        for (int k = 0; k < 128; k += 4) {
            float st0 = s_state[(k + 0) * 32 + l];
            float st1 = s_state[(k + 1) * 32 + l];
            float st2 = s_state[(k + 2) * 32 + l];
            float st3 = s_state[(k + 3) * 32 + l];
            #pragma unroll
            for (int r = 0; r < 4; r++) {
                float4 kc = *(const float4*)&s_kcd[(r0 + r) * 128 + k];
                float4 qc = *(const float4*)&s_qg[(r0 + r) * 128 + k];
                accV[r] -= kc.x * st0; accV[r] -= kc.y * st1;
                accV[r] -= kc.z * st2; accV[r] -= kc.w * st3;
                accO[r] += qc.x * st0; accO[r] += qc.y * st1;
                accO[r] += qc.z * st2; accO[r] += qc.w * st3;
            }
        }
        #pragma unroll
        for (int r = 0; r < 4; r++) s_vn[(r0 + r) * 32 + l] = accV[r];
        __syncthreads();

        // Phase B: o += attn @ v_new ; write out
        for (int c = 0; c < 64; c += 4) {
            float v0 = s_vn[(c + 0) * 32 + l];
            float v1 = s_vn[(c + 1) * 32 + l];
            float v2 = s_vn[(c + 2) * 32 + l];
            float v3 = s_vn[(c + 3) * 32 + l];
            #pragma unroll
            for (int r = 0; r < 4; r++) {
                float4 a = *(const float4*)&s_attn[(r0 + r) * 64 + c];
                accO[r] += a.x * v0; accO[r] += a.y * v1;
                accO[r] += a.z * v2; accO[r] += a.w * v3;
            }
        }
        {
            const size_t obase =
                ((size_t)(b * S_ + n * CHK) * H_ + h) * DV + vb * 32;
            #pragma unroll
            for (int r = 0; r < 4; r++)
                out[obase + (size_t)(r0 + r) * (H_ * DV) + l] = accO[r];
        }

        // Phase C: state = state * e^{g_last} + kd^T @ v_new
        // thread (w,l) owns k-rows w*8..w*8+7, col l
        {
            const int kr0 = w * 8;
            float eg = g_egl[t];
            float sacc[8];
            #pragma unroll
            for (int rr = 0; rr < 8; rr++)
                sacc[rr] = s_state[(kr0 + rr) * 32 + l] * eg;
            for (int c = 0; c < 64; c++) {
                float vn = s_vn[c * 32 + l];
                float4 kda = *(const float4*)&s_kd[c * 128 + kr0];
                float4 kdb = *(const float4*)&s_kd[c * 128 + kr0 + 4];
                sacc[0] += kda.x * vn; sacc[1] += kda.y * vn;
                sacc[2] += kda.z * vn; sacc[3] += kda.w * vn;
                sacc[4] += kdb.x * vn; sacc[5] += kdb.y * vn;
                sacc[6] += kdb.z * vn; sacc[7] += kdb.w * vn;
            }
            #pragma unroll
            for (int rr = 0; rr < 8; rr++)
                s_state[(kr0 + rr) * 32 + l] = sacc[rr];
        }
        __syncthreads();
    }
}

// ---------------------------------------------------------------------------
extern "C" void kernel_launch(void* const* d_in, const int* in_sizes, int n_in,
                              void* d_out, int out_size)
{
    const float* q    = (const float*)d_in[0];
    const float* k    = (const float*)d_in[1];
    const float* v    = (const float*)d_in[2];
    const float* g    = (const float*)d_in[3];
    const float* beta = (const float*)d_in[4];
    float* out = (float*)d_out;

    const int p1s = P1_SMEM_FLOATS * 4;
    const int p2s = P2_SMEM_FLOATS * 4;
    cudaFuncSetAttribute(p1_kernel, cudaFuncAttributeMaxDynamicSharedMemorySize, p1s);
    cudaFuncSetAttribute(p2_kernel, cudaFuncAttributeMaxDynamicSharedMemorySize, p2s);

    p1_kernel<<<NTILE, 256, p1s>>>(q, k, v, g, beta);
    p2_kernel<<<NBH * 4, 512, p2s>>>(out);
}

// round 6
// speedup vs baseline: 2.3886x; 1.0563x over previous
#include <cuda_runtime.h>
#include <cuda_bf16.h>
#include <math.h>

// Problem constants
#define B_ 2
#define S_ 4096
#define H_ 16
#define DK 128
#define DV 128
#define CHK 64
#define NCH (S_ / CHK)          // 64 chunks
#define NBH (B_ * H_)           // 32
#define NTILE (NBH * NCH)       // 2048 tiles

typedef unsigned long long u64;

// packed f32x2 FMA (sm_100+): 2 lane-FMAs per instruction
__device__ __forceinline__ u64 ffma2(u64 a, u64 b, u64 c) {
    u64 d;
    asm("fma.rn.f32x2 %0, %1, %2, %3;" : "=l"(d) : "l"(a), "l"(b), "l"(c));
    return d;
}
__device__ __forceinline__ float fold2(u64 v) {
    float x, y;
    asm("mov.b64 {%0,%1}, %2;" : "=f"(x), "=f"(y) : "l"(v));
    return x + y;
}

// Scratch (device globals: allocation-free rule)
__device__ float g_u   [NTILE * CHK * DV];   // 64 MB
__device__ float g_kcd [NTILE * CHK * DK];   // 64 MB
__device__ float g_qg  [NTILE * CHK * DK];   // 64 MB
__device__ float g_kd  [NTILE * CHK * DK];   // 64 MB, pair-over-c layout: (c>>1)*256 + 2k + (c&1)
__device__ float g_attn[NTILE * CHK * CHK];  // 32 MB
__device__ float g_egl [NTILE];              // exp(g_last) per tile

#define SKP 130   // sk pitch: even (8B-aligned float2 column loads), conflict-free col access

// p1 smem: sq 8192 + sk 8320 + sv 8192 + sA 4096 + sU 16384 + 512 misc
#define P1_SMEM_FLOATS (8192 + 8320 + 8192 + 4096 + 16384 + 512)
// p2 smem: state 4096 + kcd 8192 + qg 8192 + kd 8192 + attn 4096 + u 2048 + vn 2048
#define P2_SMEM_FLOATS (4096 + 8192 + 8192 + 8192 + 4096 + 2048 + 2048)

// ---------------------------------------------------------------------------
// Phase 1: per-(b,h,chunk) preprocessing. grid = 2048, block = 256.
// ---------------------------------------------------------------------------
__global__ __launch_bounds__(256, 1)
void p1_kernel(const float* __restrict__ q_in, const float* __restrict__ k_in,
               const float* __restrict__ v_in, const float* __restrict__ g_in,
               const float* __restrict__ b_in)
{
    extern __shared__ float sm[];
    float* sq   = sm;              // [64][128]
    float* sk   = sq + 8192;       // [64][SKP=130]
    float* sv   = sk + 8320;       // [64][128]  (prescaled by beta)
    float* sA   = sv + 8192;       // [64][64]
    float* sU   = sA + 4096;       // pair layout: (i>>1)*512 + 2c + (i&1)
    float* s_g    = sU + 16384;    // 64
    float* s_beta = s_g + 64;      // 64
    float* s_gcs  = s_beta + 64;   // 64
    float* s_ec   = s_gcs + 64;    // 64 exp(gcs)
    float* s_el   = s_ec + 64;     // 64 exp(g_last - gcs)
    float* s_bfe  = s_el + 64;     // 64 beta*exp(gcs)
    float* s_rn   = s_bfe + 64;    // 128

    const int t   = blockIdx.x;
    const int n   = t & (NCH - 1);
    const int bh  = t >> 6;
    const int b   = bh >> 4;
    const int h   = bh & 15;
    const int tid = threadIdx.x;

    const size_t base = ((size_t)(b * S_ + n * CHK) * H_ + h) * DK;

    // Load q/k/v tile
    for (int p = tid; p < 2048; p += 256) {
        int row = p >> 5;
        int c   = (p & 31) * 4;
        float4 qv = *(const float4*)&q_in[base + (size_t)row * 2048 + c];
        float4 kv = *(const float4*)&k_in[base + (size_t)row * 2048 + c];
        float4 vv = *(const float4*)&v_in[base + (size_t)row * 2048 + c];
        sq[row * 128 + c + 0] = qv.x; sq[row * 128 + c + 1] = qv.y;
        sq[row * 128 + c + 2] = qv.z; sq[row * 128 + c + 3] = qv.w;
        sk[row * SKP + c + 0] = kv.x; sk[row * SKP + c + 1] = kv.y;
        sk[row * SKP + c + 2] = kv.z; sk[row * SKP + c + 3] = kv.w;
        sv[row * 128 + c + 0] = vv.x; sv[row * 128 + c + 1] = vv.y;
        sv[row * 128 + c + 2] = vv.z; sv[row * 128 + c + 3] = vv.w;
    }
    if (tid < 64) {
        int s = n * CHK + tid;
        s_g[tid]    = g_in[(size_t)(b * S_ + s) * H_ + h];
        s_beta[tid] = b_in[(size_t)(b * S_ + s) * H_ + h];
    }
    __syncthreads();

    // cumsum of g (cheap serial; runs alongside the norm phase)
    if (tid == 0) {
        float c = 0.f;
        for (int i = 0; i < 64; i++) { c += s_g[i]; s_gcs[i] = c; }
    }
    // row L2 norms: 4 threads per row
    {
        int row = tid >> 2, part = tid & 3;
        float aq = 0.f, ak = 0.f;
        for (int d = part * 32; d < part * 32 + 32; d++) {
            float a = sq[row * 128 + d]; aq += a * a;
            float c = sk[row * SKP + d]; ak += c * c;
        }
        aq += __shfl_xor_sync(0xffffffff, aq, 1);
        aq += __shfl_xor_sync(0xffffffff, aq, 2);
        ak += __shfl_xor_sync(0xffffffff, ak, 1);
        ak += __shfl_xor_sync(0xffffffff, ak, 2);
        if (part == 0) {
            s_rn[row]      = rsqrtf(aq + 1e-6f) * 0.08838834764831843f; // * Dk^-0.5
            s_rn[64 + row] = rsqrtf(ak + 1e-6f);
        }
    }
    __syncthreads();

    // scale q, k; prescale v by beta; exp tables
    for (int p = tid; p < 8192; p += 256) {
        int row = p >> 7, c = p & 127;
        sq[p] *= s_rn[row];
        sk[row * SKP + c] *= s_rn[64 + row];
        sv[p] *= s_beta[row];
    }
    if (tid < 64) {
        float e = expf(s_gcs[tid]);
        s_ec[tid]  = e;
        s_el[tid]  = expf(s_gcs[63] - s_gcs[tid]);
        s_bfe[tid] = s_beta[tid] * e;
    }
    __syncthreads();

    // A = strict_tril(kb . k^T * decay);  attn = tril(q . k^T * decay) -> global
    // Paired over d: FFMA2, half the instructions of the scalar version.
    const int w = tid >> 5, l = tid & 31;
    {
        u64 accA2[8][2], accQ2[8][2];
        #pragma unroll
        for (int r = 0; r < 8; r++) {
            accA2[r][0] = accA2[r][1] = 0ull;
            accQ2[r][0] = accQ2[r][1] = 0ull;
        }
        for (int d = 0; d < 128; d += 2) {
            u64 k0p = *(const u64*)&sk[l * SKP + d];
            u64 k1p = *(const u64*)&sk[(l + 32) * SKP + d];
            #pragma unroll
            for (int r = 0; r < 8; r++) {
                u64 kip = *(const u64*)&sk[(w * 8 + r) * SKP + d];
                u64 qip = *(const u64*)&sq[(w * 8 + r) * 128 + d];
                accA2[r][0] = ffma2(kip, k0p, accA2[r][0]);
                accA2[r][1] = ffma2(kip, k1p, accA2[r][1]);
                accQ2[r][0] = ffma2(qip, k0p, accQ2[r][0]);
                accQ2[r][1] = ffma2(qip, k1p, accQ2[r][1]);
            }
        }
        float* gattn = g_attn + (size_t)t * (CHK * CHK);
        #pragma unroll
        for (int r = 0; r < 8; r++) {
            int i = w * 8 + r;
            #pragma unroll
            for (int c2 = 0; c2 < 2; c2++) {
                int jj  = l + c2 * 32;
                float dec = (i >= jj) ? expf(s_gcs[i] - s_gcs[jj]) : 0.f;
                sA[i * 64 + jj]    = (i > jj) ? fold2(accA2[r][c2]) * s_beta[i] * dec : 0.f;
                gattn[i * 64 + jj] = fold2(accQ2[r][c2]) * dec;
            }
        }
    }
    __syncthreads();

    // Fused forward substitution: (I + A) X = [ v*beta | k*beta*e^gcs ]
    // One column per thread, zero barriers, paired over m.
    {
        const int c  = tid;
        const int cc = c & 127;
        const bool isV = (c < 128);
        for (int i = 0; i < 64; i++) {
            float acc = isV ? sv[i * 128 + cc]
                            : sk[i * SKP + cc] * s_bfe[i];
            u64 s2a = 0ull, s2b = 0ull;
            const int m2e = i >> 1;
            int m2 = 0;
            for (; m2 + 1 < m2e; m2 += 2) {
                s2a = ffma2(*(const u64*)&sA[i * 64 + 2 * m2],
                            *(const u64*)&sU[m2 * 512 + 2 * c], s2a);
                s2b = ffma2(*(const u64*)&sA[i * 64 + 2 * m2 + 2],
                            *(const u64*)&sU[(m2 + 1) * 512 + 2 * c], s2b);
            }
            for (; m2 < m2e; m2++)
                s2a = ffma2(*(const u64*)&sA[i * 64 + 2 * m2],
                            *(const u64*)&sU[m2 * 512 + 2 * c], s2a);
            float sub = fold2(s2a) + fold2(s2b);
            if (i & 1)
                sub += sA[i * 64 + (i - 1)] * sU[((i - 1) >> 1) * 512 + 2 * c];
            float val = acc - sub;
            sU[(i >> 1) * 512 + 2 * c + (i & 1)] = val;
            if (isV) g_u  [(size_t)t * (CHK * DV) + i * 128 + cc] = val;
            else     g_kcd[(size_t)t * (CHK * DK) + i * 128 + cc] = val;
        }
    }

    // qg = q * e^gcs (row-major); kd in pair-over-c layout: (c>>1)*256 + 2k + (c&1)
    {
        float* gq = g_qg + (size_t)t * (CHK * DK);
        float* gd = g_kd + (size_t)t * (CHK * DK);
        for (int p = tid; p < 8192; p += 256) {
            int row = p >> 7, c = p & 127;
            gq[p] = sq[p] * s_ec[row];
        }
        for (int p = tid; p < 4096; p += 256) {
            int rp = p >> 7, k = p & 127;   // rp = c-pair index
            float2 val;
            val.x = sk[(2 * rp)     * SKP + k] * s_el[2 * rp];
            val.y = sk[(2 * rp + 1) * SKP + k] * s_el[2 * rp + 1];
            *(float2*)&gd[rp * 256 + 2 * k] = val;
        }
        if (tid == 0) g_egl[t] = expf(s_gcs[63]);
    }
}

// ---------------------------------------------------------------------------
// Phase 2: sequential scan. grid = 128 (32 bh x 4 Dv-blocks), block = 512.
// State layout (pair-over-k): (k>>1)*64 + 2l + (k&1)
// vn layout (pair-over-row): (r>>1)*64 + 2l + (r&1)
// ---------------------------------------------------------------------------
__global__ __launch_bounds__(512, 1)
void p2_kernel(float* __restrict__ out)
{
    extern __shared__ float sm[];
    float* s_state = sm;                 // 4096
    float* s_kcd   = s_state + 4096;     // [64][128] row-major
    float* s_qg    = s_kcd + 8192;       // [64][128] row-major
    float* s_kd    = s_qg + 8192;        // pair-over-c layout (as in g_kd)
    float* s_attn  = s_kd + 8192;        // [64][64] row-major
    float* s_u     = s_attn + 4096;      // [64][32] row-major
    float* s_vn    = s_u + 2048;         // pair-over-row layout

    const int bx = blockIdx.x;
    const int bh = bx >> 2;
    const int vb = bx & 3;
    const int b  = bh >> 4;
    const int h  = bh & 15;
    const int tid = threadIdx.x;
    const int w = tid >> 5, l = tid & 31;   // 16 warps

    for (int p = tid; p < 4096; p += 512) s_state[p] = 0.f;
    __syncthreads();

    for (int n = 0; n < NCH; n++) {
        const size_t t = (size_t)bh * NCH + n;

        // stage this chunk's matrices (512 threads)
        {
            const float4* gk = (const float4*)(g_kcd + t * (CHK * DK));
            const float4* gq = (const float4*)(g_qg  + t * (CHK * DK));
            const float4* gd = (const float4*)(g_kd  + t * (CHK * DK));
            const float4* ga = (const float4*)(g_attn + t * (CHK * CHK));
            #pragma unroll
            for (int it = 0; it < 4; it++) {
                int p = tid + it * 512;
                ((float4*)s_kcd)[p] = gk[p];
                ((float4*)s_qg)[p]  = gq[p];
                ((float4*)s_kd)[p]  = gd[p];
            }
            #pragma unroll
            for (int it = 0; it < 2; it++) {
                int p = tid + it * 512;
                ((float4*)s_attn)[p] = ga[p];
            }
            {
                int row = tid >> 3, c4 = (tid & 7) * 4;
                ((float4*)s_u)[tid] =
                    *(const float4*)&g_u[t * (CHK * DV) + row * 128 + vb * 32 + c4];
            }
        }
        __syncthreads();

        // Phase A: v_new = u - kcd @ state ; o1 = qg @ state  (4 rows per warp)
        const int r0 = w * 4;
        u64 sV[4], sO[4];
        #pragma unroll
        for (int r = 0; r < 4; r++) { sV[r] = 0ull; sO[r] = 0ull; }

        for (int k4 = 0; k4 < 32; k4++) {
            u64 st01 = *(const u64*)&s_state[(2 * k4)     * 64 + 2 * l];
            u64 st23 = *(const u64*)&s_state[(2 * k4 + 1) * 64 + 2 * l];
            #pragma unroll
            for (int r = 0; r < 4; r++) {
                ulonglong2 kc = *(const ulonglong2*)&s_kcd[(r0 + r) * 128 + 4 * k4];
                ulonglong2 qc = *(const ulonglong2*)&s_qg [(r0 + r) * 128 + 4 * k4];
                sV[r] = ffma2(kc.x, st01, sV[r]);
                sV[r] = ffma2(kc.y, st23, sV[r]);
                sO[r] = ffma2(qc.x, st01, sO[r]);
                sO[r] = ffma2(qc.y, st23, sO[r]);
            }
        }
        #pragma unroll
        for (int r = 0; r < 4; r += 2) {
            float2 pr;
            pr.x = s_u[(r0 + r)     * 32 + l] - fold2(sV[r]);
            pr.y = s_u[(r0 + r + 1) * 32 + l] - fold2(sV[r + 1]);
            *(float2*)&s_vn[((r0 + r) >> 1) * 64 + 2 * l] = pr;
        }
        __syncthreads();

        // Phase B: o += attn @ v_new ; write out
        for (int c4 = 0; c4 < 16; c4++) {
            u64 vn01 = *(const u64*)&s_vn[(2 * c4)     * 64 + 2 * l];
            u64 vn23 = *(const u64*)&s_vn[(2 * c4 + 1) * 64 + 2 * l];
            #pragma unroll
            for (int r = 0; r < 4; r++) {
                ulonglong2 a = *(const ulonglong2*)&s_attn[(r0 + r) * 64 + 4 * c4];
                sO[r] = ffma2(a.x, vn01, sO[r]);
                sO[r] = ffma2(a.y, vn23, sO[r]);
            }
        }
        {
            const size_t obase =
                ((size_t)(b * S_ + n * CHK) * H_ + h) * DV + vb * 32;
            #pragma unroll
            for (int r = 0; r < 4; r++)
                out[obase + (size_t)(r0 + r) * (H_ * DV) + l] = fold2(sO[r]);
        }

        // Phase C: state = state * e^{g_last} + kd^T @ v_new
        // thread (w,l) owns k-rows kr0..kr0+7, col l; paired over c.
        {
            const int kr0 = w * 8;
            u64 s2[8];
            #pragma unroll
            for (int j = 0; j < 8; j++) s2[j] = 0ull;
            for (int c2 = 0; c2 < 32; c2++) {
                u64 vnp = *(const u64*)&s_vn[c2 * 64 + 2 * l];
                #pragma unroll
                for (int j = 0; j < 4; j++) {
                    ulonglong2 kd = *(const ulonglong2*)&s_kd[c2 * 256 + 2 * (kr0 + 2 * j)];
                    s2[2 * j]     = ffma2(kd.x, vnp, s2[2 * j]);
                    s2[2 * j + 1] = ffma2(kd.y, vnp, s2[2 * j + 1]);
                }
            }
            float eg = g_egl[t];
            #pragma unroll
            for (int j = 0; j < 4; j++) {
                float2 old = *(const float2*)&s_state[(kr0 / 2 + j) * 64 + 2 * l];
                float2 nw;
                nw.x = old.x * eg + fold2(s2[2 * j]);
                nw.y = old.y * eg + fold2(s2[2 * j + 1]);
                *(float2*)&s_state[(kr0 / 2 + j) * 64 + 2 * l] = nw;
            }
        }
        __syncthreads();
    }
}

// ---------------------------------------------------------------------------
extern "C" void kernel_launch(void* const* d_in, const int* in_sizes, int n_in,
                              void* d_out, int out_size)
{
    const float* q    = (const float*)d_in[0];
    const float* k    = (const float*)d_in[1];
    const float* v    = (const float*)d_in[2];
    const float* g    = (const float*)d_in[3];
    const float* beta = (const float*)d_in[4];
    float* out = (float*)d_out;

    const int p1s = P1_SMEM_FLOATS * 4;
    const int p2s = P2_SMEM_FLOATS * 4;
    cudaFuncSetAttribute(p1_kernel, cudaFuncAttributeMaxDynamicSharedMemorySize, p1s);
    cudaFuncSetAttribute(p2_kernel, cudaFuncAttributeMaxDynamicSharedMemorySize, p2s);

    p1_kernel<<<NTILE, 256, p1s>>>(q, k, v, g, beta);
    p2_kernel<<<NBH * 4, 512, p2s>>>(out);
}